// round 11
// baseline (speedup 1.0000x reference)
#include <cuda_runtime.h>
#include <math.h>

#define DIM 4096
#define DIAG_BLOCKS 128   // 128 blocks x 32 threads = 4096 diagonal elements

// First 30 primes (== P_DIAG for DIM=4096).
__constant__ int c_primes[30] = {
    2, 3, 5, 7, 11, 13, 17, 19, 23, 29,
    31, 37, 41, 43, 47, 53, 59, 61, 67, 71,
    73, 79, 83, 89, 97, 101, 103, 107, 109, 113};

// ---------------------------------------------------------------------------
// Structure (from R5 evidence: driver memset ~32 TB/s effective, ~6x faster
// per byte than any SM store kernel measured in R6-R10):
//   node 1: cudaMemsetAsync zero-fill of the whole 64 MiB output
//   node 2: this kernel — 4096 fp64 diagonal elements, one per thread,
//           one warp per SM (128 blocks) so each element's log/exp/cos
//           latency chain runs fully parallel; scalar float store onto
//           the diagonal (4096 scattered 4 B stores, distinct L2 sectors).
//
// Math reduction (validated R5-R10, rel_err 1.802e-6):
//  * Off-diagonal prime terms are purely imaginary -> cancel EXACTLY under
//    0.5*(H + H^dagger); Re(H) (float32 output) is a pure diagonal.
//  * reg = max(1e-22, ||H||_F*1e-18) ~ 3.6e-18 is additively invisible in
//    float32 -> Frobenius reduction dropped.
// ---------------------------------------------------------------------------
__global__ __launch_bounds__(32)
void diag_kernel(const float* sr_p, const float* si_p, const float* th_p,
                 float* __restrict__ out) {
    const unsigned int t = blockIdx.x * 32u + threadIdx.x;  // 0..4095
    const int n = (int)t + 1;                               // 1..4096

    const double ZETA2 = 1.6449340668482264365;  // pi^2/6
    const double CUTOFF = 1e-80;
    const double sr = sr_p ? (double)*sr_p : 0.5;
    const double si = si_p ? (double)*si_p : 14.134725141734693;
    const double th = th_p ? (double)*th_p : 1e-22;

    const double logn = log((double)n);
    const bool in_range = (fabs(sr) < 30.0) && (fabs(si) < 500.0);
    const bool safe = (-sr * logn) > -80.0;
    // Re(exp(-s ln n)) = exp(-sr ln n) * cos(si ln n)
    double d = (in_range || safe) ? exp(-sr * logn) * cos(si * logn)
                                  : CUTOFF;
    if (n <= 113) {
        bool isp = false;
#pragma unroll
        for (int j = 0; j < 30; j++) isp = isp || (n == c_primes[j]);
        if (isp) {
            const double corr = fmin(sqrt(sr * sr + si * si), 5.0);
            d += th * logn * corr * (ZETA2 / (double)n);
        }
    }

    // Diagonal element (t, t); last byte written = 4095*4097*4 + 4 = 64 MiB.
    out[(size_t)t * (DIM + 1)] = (float)d;
}

extern "C" void kernel_launch(void* const* d_in, const int* in_sizes, int n_in,
                              void* d_out, int out_size) {
    (void)in_sizes;
    const float* sr = (n_in >= 1) ? (const float*)d_in[0] : 0;
    const float* si = (n_in >= 2) ? (const float*)d_in[1] : 0;
    const float* th = (n_in >= 3) ? (const float*)d_in[2] : 0;

    // Driver/graph memset node: measured (R5) far faster than SM stores.
    cudaMemsetAsync(d_out, 0, (size_t)out_size * 4u, 0);

    diag_kernel<<<DIAG_BLOCKS, 32>>>(sr, si, th, (float*)d_out);
}

// round 12
// speedup vs baseline: 1.1476x; 1.1476x over previous
#include <cuda_runtime.h>
#include <math.h>

#define DIM 4096

// First 30 primes (== P_DIAG for DIM=4096).
__constant__ int c_primes[30] = {
    2, 3, 5, 7, 11, 13, 17, 19, 23, 29,
    31, 37, 41, 43, 47, 53, 59, 61, 67, 71,
    73, 79, 83, 89, 97, 101, 103, 107, 109, 113};

// ---------------------------------------------------------------------------
// node 1: cudaMemsetAsync zero-fill (measured ~7 us for 64 MiB — the fastest
//         fill primitive seen across R6-R11).
// node 2: this kernel — 4096 diagonal elements, one per thread, FP32
//         transcendentals (R11 showed the fp64 chain alone costs ~8 us;
//         fp32 cuts the dependency chain ~15x). Output dtype is float32 and
//         the tolerance is 1e-3, so fp32 math is 50x inside budget.
//
// Precision-critical piece: the cosine phase si*ln(n) reaches ~118 rad.
// Computed in fp64 (1 mul) and range-reduced to [-pi,pi] in fp64 (2 ops),
// then cosf on the reduced argument — accurate even under --use_fast_math.
//
// Math reduction (validated R5-R11, rel_err 1.802e-6 in the fp64 version):
//  * Off-diagonal prime terms are purely imaginary -> cancel EXACTLY under
//    0.5*(H + H^dagger); Re(H) (float32) is a pure diagonal.
//  * reg ~ 3.6e-18 additively invisible in float32 -> reduction dropped.
// ---------------------------------------------------------------------------
__global__ __launch_bounds__(128)
void diag_kernel(const float* sr_p, const float* si_p, const float* th_p,
                 float* __restrict__ out) {
    const unsigned int t = blockIdx.x * 128u + threadIdx.x;  // 0..4095
    const int n = (int)t + 1;                                // 1..4096

    const float sr = sr_p ? *sr_p : 0.5f;
    const float si = si_p ? *si_p : 14.134725141734693f;
    const float th = th_p ? *th_p : 1e-22f;

    const float logn = logf((float)n);

    // Amplitude: exp(-sr*ln n) = n^(-sr)   (fp32; values in [4096^-sr, 1])
    const float amp = expf(-sr * logn);

    // Phase: si*ln n, fp64 product + fp64 2*pi range reduction -> [-pi,pi]
    const double phi = (double)si * (double)logn;
    const double k = rint(phi * 0.15915494309189533576);   // 1/(2*pi)
    const float r = (float)(phi - k * 6.2831853071795864769);
    const float c = cosf(r);

    const bool in_range = (fabsf(sr) < 30.0f) && (fabsf(si) < 500.0f);
    const bool safe = (-sr * logn) > -80.0f;
    // CUTOFF=1e-80 underflows to 0 in fp32 — identical to the reference
    // value after its own complex128 -> float32 lowering.
    float d = (in_range || safe) ? amp * c : 0.0f;

    if (n <= 113) {
        bool isp = false;
#pragma unroll
        for (int j = 0; j < 30; j++) isp = isp || (n == c_primes[j]);
        if (isp) {
            const float corr = fminf(sqrtf(sr * sr + si * si), 5.0f);
            const float ZETA2 = 1.6449340668482264f;  // pi^2/6
            d += th * logn * corr * (ZETA2 / (float)n);
        }
    }

    // Diagonal element (t, t); last byte = 4095*4097*4 + 4 = 64 MiB exactly.
    out[(size_t)t * (DIM + 1)] = d;
}

extern "C" void kernel_launch(void* const* d_in, const int* in_sizes, int n_in,
                              void* d_out, int out_size) {
    (void)in_sizes;
    const float* sr = (n_in >= 1) ? (const float*)d_in[0] : 0;
    const float* si = (n_in >= 2) ? (const float*)d_in[1] : 0;
    const float* th = (n_in >= 3) ? (const float*)d_in[2] : 0;

    // Fastest measured fill primitive: driver memset node (~7 us / 64 MiB).
    cudaMemsetAsync(d_out, 0, (size_t)out_size * 4u, 0);

    // 32 blocks x 128 threads = 4096 diagonal elements, fp32 latency chain.
    diag_kernel<<<32, 128>>>(sr, si, th, (float*)d_out);
}

// round 15
// speedup vs baseline: 1.4775x; 1.2875x over previous
#include <cuda_runtime.h>
#include <math.h>

#define DIM 4096
#define DIAG_BLOCKS 32      // 32 * 128 threads = 4096 diagonal elements
#define FILL_BLOCKS 16384   // 16384 * 256 threads * 16 B = 64 MiB exactly

// First 30 primes (== P_DIAG for DIM=4096).
__constant__ int c_primes[30] = {
    2, 3, 5, 7, 11, 13, 17, 19, 23, 29,
    31, 37, 41, 43, 47, 53, 59, 61, 67, 71,
    73, 79, 83, 89, 97, 101, 103, 107, 109, 113};

// ---------------------------------------------------------------------------
// ONE kernel, ZERO synchronization, disjoint writes (R10 structure, 15.1 us).
//  * Blocks [0, 32): diagonal, one element/thread, FIRST in the grid so the
//    compute hides under the fill (R9 measured a 4 us tail when appended).
//    fp32 math with fp64 phase reduction (R12-validated, rel_err 2.46e-6;
//    tolerance is 1e-3) — fewer registers than the fp64 path, shorter chain.
//  * Blocks [32, 16416): the empirically-fastest fill shape (1 float4 per
//    thread), store predicated OFF for the 4096 diagonal-containing slots.
//    Measured at 5.45 TB/s = the path-independent LTS cap; this is the
//    chip floor for the mandatory 64 MiB of stores (TMA is NOT faster:
//    LTS cap is path-independent; two bulk-S2G attempts also faulted).
// Address sets are disjoint -> no ordering, no flags, no atomics.
//
// Math reduction (validated R5-R12):
//  * Off-diagonal prime terms are purely imaginary -> cancel EXACTLY under
//    0.5*(H + H^dagger); Re(H) (float32 output) is a pure diagonal.
//  * reg = max(1e-22, ||H||_F*1e-18) ~ 3.6e-18 is additively invisible in
//    float32 -> Frobenius reduction dropped entirely.
// ---------------------------------------------------------------------------
__global__ __launch_bounds__(256)
void build_kernel(const float* sr_p, const float* si_p, const float* th_p,
                  float4* __restrict__ out) {
    const unsigned int bid = blockIdx.x;

    if (bid >= DIAG_BLOCKS) {
        // -------- streaming zero fill (skip diagonal slots) --------
        const unsigned int idx = (bid - DIAG_BLOCKS) * 256u + threadIdx.x;
        const unsigned int row = idx >> 10;     // 1024 float4 per matrix row
        const unsigned int col4 = idx & 1023u;
        if (col4 != (row >> 2)) {
            out[idx] = make_float4(0.f, 0.f, 0.f, 0.f);
        }
        return;
    }

    // -------- diagonal writer blocks (wave-1 resident) --------
    if (threadIdx.x >= 128) return;
    const unsigned int t = bid * 128u + threadIdx.x;   // 0..4095
    const int n = (int)t + 1;                          // 1..4096

    const float sr = sr_p ? *sr_p : 0.5f;
    const float si = si_p ? *si_p : 14.134725141734693f;
    const float th = th_p ? *th_p : 1e-22f;

    const float logn = logf((float)n);
    const float amp = expf(-sr * logn);        // n^(-sr)

    // Phase si*ln(n) reaches ~118 rad: fp64 product + fp64 2*pi range
    // reduction to [-pi,pi], then fp32 cosine (accurate on reduced arg).
    const double phi = (double)si * (double)logn;
    const double kq = rint(phi * 0.15915494309189533576);   // 1/(2*pi)
    const float r = (float)(phi - kq * 6.2831853071795864769);
    const float c = cosf(r);

    const bool in_range = (fabsf(sr) < 30.0f) && (fabsf(si) < 500.0f);
    const bool safe = (-sr * logn) > -80.0f;
    // CUTOFF 1e-80 underflows to 0 in fp32, matching the reference's own
    // complex128 -> float32 lowering.
    float d = (in_range || safe) ? amp * c : 0.0f;

    if (n <= 113) {
        bool isp = false;
#pragma unroll
        for (int j = 0; j < 30; j++) isp = isp || (n == c_primes[j]);
        if (isp) {
            const float corr = fminf(sqrtf(sr * sr + si * si), 5.0f);
            const float ZETA2 = 1.6449340668482264f;  // pi^2/6
            d += th * logn * corr * (ZETA2 / (float)n);
        }
    }

    // Write the diagonal-containing float4 slot (disjoint from fill writes).
    float4 v = make_float4(0.f, 0.f, 0.f, 0.f);
    switch (t & 3u) {
        case 0:  v.x = d; break;
        case 1:  v.y = d; break;
        case 2:  v.z = d; break;
        default: v.w = d; break;
    }
    out[(size_t)t * 1024u + (t >> 2)] = v;
}

extern "C" void kernel_launch(void* const* d_in, const int* in_sizes, int n_in,
                              void* d_out, int out_size) {
    (void)in_sizes; (void)out_size;
    const float* sr = (n_in >= 1) ? (const float*)d_in[0] : 0;
    const float* si = (n_in >= 2) ? (const float*)d_in[1] : 0;
    const float* th = (n_in >= 3) ? (const float*)d_in[2] : 0;

    build_kernel<<<DIAG_BLOCKS + FILL_BLOCKS, 256>>>(sr, si, th,
                                                     (float4*)d_out);
}